// round 9
// baseline (speedup 1.0000x reference)
#include <cuda_runtime.h>
#include <math.h>

#define BB 128
#define TT 256
#define DD 256
#define NSTK 32
#define ZO 1e-6f

// scratch (no allocations allowed)
__device__ float d_gbuf[BB * TT];

__device__ __forceinline__ float eluf(float v) { return v > 0.f ? v : expm1f(v); }

// ---------------------------------------------------------------------------
// Pass 1: g[b,t] = elu(cos(latch_enable, x[b,t])) — one warp per (b,t) row.
// ||le|| computed redundantly per warp (3rd butterfly chain, latency-free).
// ---------------------------------------------------------------------------
__global__ void gpass_kernel(const float* __restrict__ x, const float* __restrict__ le) {
    int warp = (blockIdx.x * blockDim.x + threadIdx.x) >> 5;
    int lane = threadIdx.x & 31;
    if (warp >= BB * TT) return;
    const float4* xr = (const float4*)(x + (size_t)warp * DD);
    const float4* lr = (const float4*)le;
    float h1 = 0.f, h2 = 0.f, h0 = 0.f;
#pragma unroll
    for (int i = 0; i < 2; i++) {
        float4 xv = xr[lane * 2 + i];
        float4 lv = lr[lane * 2 + i];
        h1 += xv.x * lv.x + xv.y * lv.y + xv.z * lv.z + xv.w * lv.w;
        h2 += xv.x * xv.x + xv.y * xv.y + xv.z * xv.z + xv.w * xv.w;
        h0 += lv.x * lv.x + lv.y * lv.y + lv.z * lv.z + lv.w * lv.w;
    }
#pragma unroll
    for (int o = 16; o; o >>= 1) {
        h1 += __shfl_xor_sync(0xffffffffu, h1, o);
        h2 += __shfl_xor_sync(0xffffffffu, h2, o);
        h0 += __shfl_xor_sync(0xffffffffu, h0, o);
    }
    if (lane == 0) {
        float an = fmaxf(sqrtf(h0), 1e-8f);
        float bn = fmaxf(sqrtf(h2), 1e-8f);
        d_gbuf[warp] = eluf(h1 / (an * bn));
    }
}

// ---------------------------------------------------------------------------
// Pass 2: sequential scan. One CTA per batch element.
//   warps 0-7 (256 thr): data lanes (d = threadIdx.x), stack in registers.
//   warp 8: scalar pipeline — pop finalize + pointer/sharpen + coefficients,
//           runs CONCURRENTLY with data warps' latch+butterfly.
// One __syncthreads per step; all shared state double-buffered.
// k.w is pre-scaled by pop, so data warps never touch sqrt/div/expm1.
// ---------------------------------------------------------------------------
#define NTHR (DD + 32)

__global__ void __launch_bounds__(NTHR, 1) stack_kernel(
    const float* __restrict__ x,
    const float* __restrict__ sp,
    const float* __restrict__ shp,
    const float* __restrict__ latch_init,
    float* __restrict__ out)
{
    __shared__ float4 s_coef[2][NSTK];   // {c, a, e, pop*p}
    __shared__ float2 s_part[2][8];      // per-warp partials {h1, h2}
    __shared__ float  s_spn[8];          // partials of ||sp||^2 (prologue only)
    __shared__ float  s_g[TT];

    const int b = blockIdx.x;
    const int d = threadIdx.x;
    const int wid = d >> 5, lane = d & 31;

    float st[NSTK];
    float sp_d = 0.f, latch = 0.f, xv = 0.f;
    float ptr = 0.f, sharpen = 0.f, an_sp = 0.f;

    if (wid < 8) {
        sp_d = sp[d];
        latch = latch_init[b * DD + d];
        s_g[d] = d_gbuf[b * TT + d];     // TT == DD == 256
#pragma unroll
        for (int n = 0; n < NSTK; n++) st[n] = ZO;
        xv = x[(size_t)(b * TT) * DD + d];

        // prologue: partials for pop_0 (from latch_init) and ||sp||^2
        float h1 = sp_d * latch, h2 = latch * latch, h3 = sp_d * sp_d;
#pragma unroll
        for (int o = 16; o; o >>= 1) {
            h1 += __shfl_xor_sync(0xffffffffu, h1, o);
            h2 += __shfl_xor_sync(0xffffffffu, h2, o);
            h3 += __shfl_xor_sync(0xffffffffu, h3, o);
        }
        if (lane == 0) { s_part[0][wid] = make_float2(h1, h2); s_spn[wid] = h3; }
    } else {
        ptr = (lane == 0) ? 1.f : ZO;
        sharpen = shp[0];
    }
    __syncthreads();

    if (wid == 8) {
        float t3 = 0.f;
#pragma unroll
        for (int w = 0; w < 8; w++) t3 += s_spn[w];
        an_sp = fmaxf(sqrtf(t3), 1e-8f);
    }

    int par = 0;
    float xnext = 0.f;
    for (int t = 0; t < TT; t++) {
        par ^= 1;
        if (wid < 8) {
            int tn = (t + 1 < TT) ? t + 1 : t;
            xnext = x[((size_t)(b * TT) + tn) * DD + d];

            // latch update for this step (pop_t already uses OLD latch via s_part)
            float g = s_g[t];
            latch = fmaf(g, xv, (1.f - g) * latch);

            // partials for pop_{t+1}
            float h1 = sp_d * latch, h2 = latch * latch;
#pragma unroll
            for (int o = 16; o; o >>= 1) {
                h1 += __shfl_xor_sync(0xffffffffu, h1, o);
                h2 += __shfl_xor_sync(0xffffffffu, h2, o);
            }
            if (lane == 0) s_part[par][wid] = make_float2(h1, h2);
        } else {
            // ---- scalar warp: finalize pop_t from partials written last step ----
            float s1 = 0.f, s2 = 0.f;
#pragma unroll
            for (int w = 0; w < 8; w++) { float2 v = s_part[par ^ 1][w]; s1 += v.x; s2 += v.y; }
            float bn = fmaxf(sqrtf(s2), 1e-8f);
            float pop = eluf(__fdividef(s1, an_sp * bn));
            float push = 1.f - pop;

            // pointer update + sharpen
            float pp = __shfl_sync(0xffffffffu, ptr, (lane + 31) & 31); // ptr[n-1]
            float pq = __shfl_sync(0xffffffffu, ptr, (lane + 1) & 31);  // ptr[n+1]
            float a  = push * pp;
            float bb = pop * ptr;
            float c  = 1.f - a - bb;
            float e  = ZO * bb;
            float np = a + pop * pq;                  // push*ptr[n-1] + pop*ptr[n+1]
            float q  = fmaxf(fmaxf(np, 0.f), 1e-12f);
            q = __powf(q, sharpen);
            float qs = q;
#pragma unroll
            for (int o = 16; o; o >>= 1) qs += __shfl_xor_sync(0xffffffffu, qs, o);
            float pn = __fdividef(q, fmaxf(qs, 1e-8f));
            s_coef[par][lane] = make_float4(c, a, e, pop * pn);
            ptr = pn;
        }
        __syncthreads();

        if (wid < 8) {
            // stack update + weighted read; k.w already includes pop
            float acc = 0.f;
#pragma unroll
            for (int n = 0; n < NSTK; n++) {
                float4 k = s_coef[par][n];
                st[n] = fmaf(k.x, st[n], fmaf(k.y, xv, k.z));
                acc = fmaf(k.w, st[n], acc);
            }
            out[((size_t)(b * TT) + t) * DD + d] = acc;
            xv = xnext;
        }
    }
}

// ---------------------------------------------------------------------------
extern "C" void kernel_launch(void* const* d_in, const int* in_sizes, int n_in,
                              void* d_out, int out_size) {
    const float* x   = (const float*)d_in[0];  // [128,256,256]
    const float* sp  = (const float*)d_in[1];  // [256]
    const float* shp = (const float*)d_in[2];  // [1]
    const float* le  = (const float*)d_in[3];  // [256]
    const float* li  = (const float*)d_in[4];  // [128,256]
    float* out = (float*)d_out;                // [128,256,256]

    gpass_kernel<<<(BB * TT) / 8, 256>>>(x, le);
    stack_kernel<<<BB, NTHR>>>(x, sp, shp, li, out);
}

// round 11
// speedup vs baseline: 1.5829x; 1.5829x over previous
#include <cuda_runtime.h>
#include <math.h>

#define BB 128
#define TT 256
#define DD 256
#define NSTK 32
#define ZO 1e-6f

// scratch (no allocations allowed)
__device__ float d_gbuf[BB * TT];            // g gate per (b,t)
__device__ float d_pop[BB * TT];             // pop gate per (b,t)
__device__ float d_latch[BB * TT * DD];      // latch state after step t (33.5 MB)

__device__ __forceinline__ float eluf(float v) { return v > 0.f ? v : expm1f(v); }

// ---------------------------------------------------------------------------
// Pass 1: g[b,t] = elu(cos(latch_enable, x[b,t])) — one warp per (b,t) row.
// ---------------------------------------------------------------------------
__global__ void gpass_kernel(const float* __restrict__ x, const float* __restrict__ le) {
    int warp = (blockIdx.x * blockDim.x + threadIdx.x) >> 5;
    int lane = threadIdx.x & 31;
    if (warp >= BB * TT) return;
    const float4* xr = (const float4*)(x + (size_t)warp * DD);
    const float4* lr = (const float4*)le;
    float h1 = 0.f, h2 = 0.f, h0 = 0.f;
#pragma unroll
    for (int i = 0; i < 2; i++) {
        float4 xv = xr[lane * 2 + i];
        float4 lv = lr[lane * 2 + i];
        h1 += xv.x * lv.x + xv.y * lv.y + xv.z * lv.z + xv.w * lv.w;
        h2 += xv.x * xv.x + xv.y * xv.y + xv.z * xv.z + xv.w * xv.w;
        h0 += lv.x * lv.x + lv.y * lv.y + lv.z * lv.z + lv.w * lv.w;
    }
#pragma unroll
    for (int o = 16; o; o >>= 1) {
        h1 += __shfl_xor_sync(0xffffffffu, h1, o);
        h2 += __shfl_xor_sync(0xffffffffu, h2, o);
        h0 += __shfl_xor_sync(0xffffffffu, h0, o);
    }
    if (lane == 0) {
        float an = fmaxf(sqrtf(h0), 1e-8f);
        float bn = fmaxf(sqrtf(h2), 1e-8f);
        d_gbuf[warp] = eluf(h1 / (an * bn));
    }
}

// ---------------------------------------------------------------------------
// Pass 2: latch scan. One thread per (b,d); 256 serial FMAs; writes all
// latch states. g[b,t] is a block-wide broadcast load (same addr per block).
// ---------------------------------------------------------------------------
__global__ void latch_scan_kernel(const float* __restrict__ x,
                                  const float* __restrict__ latch_init) {
    int idx = blockIdx.x * blockDim.x + threadIdx.x;   // = b*DD + d  (DD==256)
    int b = idx >> 8;
    int d = idx & 255;
    float latch = latch_init[idx];
    const float* xp = x + (size_t)b * TT * DD + d;
    float* lp = d_latch + (size_t)b * TT * DD + d;
    const float* gp = d_gbuf + b * TT;
#pragma unroll 4
    for (int t = 0; t < TT; t++) {
        float g = gp[t];
        latch = fmaf(g, xp[(size_t)t * DD], (1.f - g) * latch);
        lp[(size_t)t * DD] = latch;
    }
}

// ---------------------------------------------------------------------------
// Pass 3: pop[b,t] = elu(cos(should_pop, latch_{t-1})); latch_{-1}=latch_init.
// One warp per (b,t).
// ---------------------------------------------------------------------------
__global__ void pop_kernel(const float* __restrict__ sp,
                           const float* __restrict__ latch_init) {
    int warp = (blockIdx.x * blockDim.x + threadIdx.x) >> 5;
    int lane = threadIdx.x & 31;
    if (warp >= BB * TT) return;
    int b = warp >> 8;       // / TT
    int t = warp & 255;      // % TT
    const float4* lr = (t == 0)
        ? (const float4*)(latch_init + (size_t)b * DD)
        : (const float4*)(d_latch + ((size_t)b * TT + (t - 1)) * DD);
    const float4* sr = (const float4*)sp;
    float h1 = 0.f, h2 = 0.f, h0 = 0.f;
#pragma unroll
    for (int i = 0; i < 2; i++) {
        float4 lv = lr[lane * 2 + i];
        float4 sv = sr[lane * 2 + i];
        h1 += lv.x * sv.x + lv.y * sv.y + lv.z * sv.z + lv.w * sv.w;
        h2 += lv.x * lv.x + lv.y * lv.y + lv.z * lv.z + lv.w * lv.w;
        h0 += sv.x * sv.x + sv.y * sv.y + sv.z * sv.z + sv.w * sv.w;
    }
#pragma unroll
    for (int o = 16; o; o >>= 1) {
        h1 += __shfl_xor_sync(0xffffffffu, h1, o);
        h2 += __shfl_xor_sync(0xffffffffu, h2, o);
        h0 += __shfl_xor_sync(0xffffffffu, h0, o);
    }
    if (lane == 0) {
        float an = fmaxf(sqrtf(h0), 1e-8f);
        float bn = fmaxf(sqrtf(h2), 1e-8f);
        d_pop[warp] = eluf(h1 / (an * bn));
    }
}

// ---------------------------------------------------------------------------
// Pass 4: main scan. One CTA per batch; 8 warps; warp w owns d-columns
// [w*32, w*32+32). Each warp REDUNDANTLY computes the identical pointer
// recurrence (lane = slot) — zero block barriers, 1 syncwarp/step.
// Coefficients exchanged via warp-private double-buffered smem.
// ---------------------------------------------------------------------------
__global__ void __launch_bounds__(DD, 1) stack_main_kernel(
    const float* __restrict__ x,
    const float* __restrict__ shp,
    float* __restrict__ out)
{
    __shared__ float4 s_coef[8][2][NSTK];  // [warp][buf][slot] {c,a,e,pop*p}
    __shared__ float  s_pop[TT];

    const int b = blockIdx.x;
    const int tid = threadIdx.x;
    const int wid = tid >> 5, lane = tid & 31;

    s_pop[tid] = d_pop[b * TT + tid];      // TT == blockDim == 256
    __syncthreads();

    const float sharpen = shp[0];
    float ptr = (lane == 0) ? 1.f : ZO;

    float st[NSTK];
#pragma unroll
    for (int n = 0; n < NSTK; n++) st[n] = ZO;

    const float* xb = x + (size_t)b * TT * DD + tid;   // column tid = wid*32+lane
    float* ob = out + (size_t)b * TT * DD + tid;

    float xv = xb[0];
    int par = 0;
    for (int t = 0; t < TT; t++) {
        int tn = (t + 1 < TT) ? t + 1 : t;
        float xnext = xb[(size_t)tn * DD];

        // --- pointer recurrence (identical in every warp; lane = slot) ---
        float pop = s_pop[t];
        float push = 1.f - pop;
        float pp = __shfl_sync(0xffffffffu, ptr, (lane + 31) & 31); // ptr[n-1]
        float pq = __shfl_sync(0xffffffffu, ptr, (lane + 1) & 31);  // ptr[n+1]
        float a  = push * pp;
        float bb = pop * ptr;
        float c  = 1.f - a - bb;
        float e  = ZO * bb;
        float np = a + pop * pq;                    // push*ptr[n-1] + pop*ptr[n+1]
        float q  = fmaxf(fmaxf(np, 0.f), 1e-12f);
        q = __powf(q, sharpen);
        float qs = q;
#pragma unroll
        for (int o = 16; o; o >>= 1) qs += __shfl_xor_sync(0xffffffffu, qs, o);
        float pn = __fdividef(q, fmaxf(qs, 1e-8f));

        s_coef[wid][par][lane] = make_float4(c, a, e, pop * pn);
        __syncwarp();

        // --- stack update + weighted read (coef broadcast from warp smem) ---
        float acc = 0.f;
#pragma unroll
        for (int n = 0; n < NSTK; n++) {
            float4 k = s_coef[wid][par][n];
            st[n] = fmaf(k.x, st[n], fmaf(k.y, xv, k.z));
            acc = fmaf(k.w, st[n], acc);
        }
        ob[(size_t)t * DD] = acc;

        ptr = pn;
        xv = xnext;
        par ^= 1;
    }
}

// ---------------------------------------------------------------------------
extern "C" void kernel_launch(void* const* d_in, const int* in_sizes, int n_in,
                              void* d_out, int out_size) {
    const float* x   = (const float*)d_in[0];  // [128,256,256]
    const float* sp  = (const float*)d_in[1];  // [256]
    const float* shp = (const float*)d_in[2];  // [1]
    const float* le  = (const float*)d_in[3];  // [256]
    const float* li  = (const float*)d_in[4];  // [128,256]
    float* out = (float*)d_out;                // [128,256,256]

    gpass_kernel<<<(BB * TT) / 8, 256>>>(x, le);
    latch_scan_kernel<<<(BB * DD) / 256, 256>>>(x, li);
    pop_kernel<<<(BB * TT) / 8, 256>>>(sp, li);
    stack_main_kernel<<<BB, DD>>>(x, shp, out);
}